// round 10
// baseline (speedup 1.0000x reference)
#include <cuda_runtime.h>
#include <cuda_bf16.h>

#define CI 16
#define CO 16
#define DEG 16
#define BSROW (1 + DEG)            // 17 ints per bs_slice row

#define THREADS 256
#define PTS_BLK 64                 // points per block (8 warps x 8 points)

// out[p,o] = sum_j sum_d radii[p*DEG+j,d] * sum_i W[d,o,i] * features[nbr(p,j),i]
// Factored: g_d[i] = sum_j r_jd * f[nbr_j,i];  out[o] = sum_{d,i} W[d,o,i] * g_d[i]
//
// Two phases, two lane mappings, ZERO shuffles:
//  Phase 1 (4 lanes/point): lane (pt,c4) accumulates g_d[4c4..+3] over ALL 16
//    neighbors (4 chunks of 4, idx+radii from padded smem, double-buffered
//    feature gathers). No reduction. g -> smem (3 STS.128).
//  Phase 2 (16 lanes/point): lane = output o, W[3][o][16] in 48 regs loaded
//    once per block (phase-1 regs dead), g via broadcast LDS.128. Full dot
//    product per lane; coalesced 128B STG per warp-round.
__global__ __launch_bounds__(THREADS)
void PeriodicConvolutionPrep_fused(
    const float* __restrict__ features,   // [P, CI]
    const float* __restrict__ radii,      // [P*DEG, 3]
    const float* __restrict__ W,          // [3, CO, CI]
    const int*   __restrict__ bs,         // [P, 1+DEG]
    float*       __restrict__ out,        // [P, CO]
    int P)
{
    __shared__ int    s_bs[PTS_BLK][20];      // idx, stride 20 ints: conflict-free
    __shared__ float4 s_r[PTS_BLK][13];       // radii, stride 13 f4 (52 fl): conflict-free
    __shared__ float  s_g[PTS_BLK][52];       // g rows, stride 52 fl: conflict-free

    const int tid  = threadIdx.x;
    const int wrp  = tid >> 5;
    const int lane = tid & 31;

    const int base   = blockIdx.x * PTS_BLK;
    const int nvalid = min(PTS_BLK, P - base);

    // ---- bulk coalesced staging: bs rows (drop count col) and radii ----
    {
        const int* bsrc = bs + (size_t)base * BSROW;
        const int  ntot = nvalid * BSROW;
        for (int k = tid; k < ntot; k += THREADS) {
            const int v = __ldg(bsrc + k);
            const int row = k / BSROW, col = k - row * BSROW;
            if (col) s_bs[row][col - 1] = v;
        }
        const float4* rsrc = (const float4*)(radii + (size_t)base * (DEG * 3));
        const int nf4 = nvalid * 12;
        for (int k = tid; k < nf4; k += THREADS) {
            const int row = k / 12, col = k - row * 12;
            s_r[row][col] = __ldg(rsrc + k);
        }
    }
    __syncthreads();

    // ================= Phase 1: 4 lanes per point, no reductions =============
    {
        const int pt3 = lane >> 2;            // point within warp (0..7)
        const int c4  = lane & 3;             // channel quad
        const int ptL = wrp * 8 + pt3;        // local point (0..63)
        const bool pv = (ptL < nvalid);
        const int ptC = pv ? ptL : 0;

        const float4* fb4 = (const float4*)features;

        float g[12];
#pragma unroll
        for (int v = 0; v < 12; v++) g[v] = 0.f;

        // double-buffered chunks of 4 neighbors
        float4 f[2][4];
        {
            const int4 id0 = *(const int4*)&s_bs[ptC][0];
            f[0][0] = __ldg(fb4 + (size_t)id0.x * 4 + c4);
            f[0][1] = __ldg(fb4 + (size_t)id0.y * 4 + c4);
            f[0][2] = __ldg(fb4 + (size_t)id0.z * 4 + c4);
            f[0][3] = __ldg(fb4 + (size_t)id0.w * 4 + c4);
        }

#pragma unroll
        for (int ch = 0; ch < 4; ch++) {
            const int slot = ch & 1;
            if (ch < 3) {
                const int4 idn = *(const int4*)&s_bs[ptC][4 * (ch + 1)];
                f[slot ^ 1][0] = __ldg(fb4 + (size_t)idn.x * 4 + c4);
                f[slot ^ 1][1] = __ldg(fb4 + (size_t)idn.y * 4 + c4);
                f[slot ^ 1][2] = __ldg(fb4 + (size_t)idn.z * 4 + c4);
                f[slot ^ 1][3] = __ldg(fb4 + (size_t)idn.w * 4 + c4);
            }
            const float4 rv0 = s_r[ptC][ch * 3 + 0];
            const float4 rv1 = s_r[ptC][ch * 3 + 1];
            const float4 rv2 = s_r[ptC][ch * 3 + 2];
            const float rr[12] = { rv0.x, rv0.y, rv0.z, rv0.w, rv1.x, rv1.y,
                                   rv1.z, rv1.w, rv2.x, rv2.y, rv2.z, rv2.w };
#pragma unroll
            for (int jj = 0; jj < 4; jj++) {
                const float4 fv = f[slot][jj];
#pragma unroll
                for (int d = 0; d < 3; d++) {
                    const float rs = rr[jj * 3 + d];
                    g[d * 4 + 0] = fmaf(rs, fv.x, g[d * 4 + 0]);
                    g[d * 4 + 1] = fmaf(rs, fv.y, g[d * 4 + 1]);
                    g[d * 4 + 2] = fmaf(rs, fv.z, g[d * 4 + 2]);
                    g[d * 4 + 3] = fmaf(rs, fv.w, g[d * 4 + 3]);
                }
            }
        }

        if (pv) {
#pragma unroll
            for (int d = 0; d < 3; d++)
                *(float4*)&s_g[ptL][d * CI + 4 * c4] =
                    make_float4(g[d * 4 + 0], g[d * 4 + 1], g[d * 4 + 2], g[d * 4 + 3]);
        }
    }

    // ---- W[3][o][16] into 48 regs; issue before the barrier to hide latency ----
    const int o = lane & 15;
    float w[48];
#pragma unroll
    for (int d = 0; d < 3; d++) {
        const float4* wrow = (const float4*)(W + ((size_t)d * CO + o) * CI);
#pragma unroll
        for (int qq = 0; qq < 4; qq++) {
            const float4 v = __ldg(wrow + qq);
            w[d * 16 + qq * 4 + 0] = v.x;
            w[d * 16 + qq * 4 + 1] = v.y;
            w[d * 16 + qq * 4 + 2] = v.z;
            w[d * 16 + qq * 4 + 3] = v.w;
        }
    }

    __syncthreads();

    // ================= Phase 2: 16 lanes per point, no reductions ============
    {
        const int ph = lane >> 4;             // half-warp = point within round
#pragma unroll
        for (int rnd = 0; rnd < 4; rnd++) {
            const int pL = rnd * 16 + wrp * 2 + ph;   // 0..63
            if (pL >= nvalid) continue;

            float a0 = 0.f, a1 = 0.f, a2 = 0.f;
#pragma unroll
            for (int d = 0; d < 3; d++) {
                const float4 v0 = *(const float4*)&s_g[pL][d * CI + 0];
                const float4 v1 = *(const float4*)&s_g[pL][d * CI + 4];
                const float4 v2 = *(const float4*)&s_g[pL][d * CI + 8];
                const float4 v3 = *(const float4*)&s_g[pL][d * CI + 12];
                a0 = fmaf(w[d*16+ 0], v0.x, a0); a0 = fmaf(w[d*16+ 1], v0.y, a0);
                a0 = fmaf(w[d*16+ 2], v0.z, a0); a0 = fmaf(w[d*16+ 3], v0.w, a0);
                a1 = fmaf(w[d*16+ 4], v1.x, a1); a1 = fmaf(w[d*16+ 5], v1.y, a1);
                a1 = fmaf(w[d*16+ 6], v1.z, a1); a1 = fmaf(w[d*16+ 7], v1.w, a1);
                a2 = fmaf(w[d*16+ 8], v2.x, a2); a2 = fmaf(w[d*16+ 9], v2.y, a2);
                a2 = fmaf(w[d*16+10], v2.z, a2); a2 = fmaf(w[d*16+11], v2.w, a2);
                a0 = fmaf(w[d*16+12], v3.x, a0); a0 = fmaf(w[d*16+13], v3.y, a0);
                a1 = fmaf(w[d*16+14], v3.z, a1); a2 = fmaf(w[d*16+15], v3.w, a2);
            }
            out[(size_t)(base + pL) * CO + o] = a0 + a1 + a2;  // 128B/warp STG
        }
    }
}

extern "C" void kernel_launch(void* const* d_in, const int* in_sizes, int n_in,
                              void* d_out, int out_size) {
    const float* features = (const float*)d_in[0];
    const float* radii    = (const float*)d_in[1];
    const float* W        = (const float*)d_in[2];
    const int*   bs       = (const int*)d_in[3];
    float*       out      = (float*)d_out;

    const int P = in_sizes[0] / CI;
    const int blocks = (P + PTS_BLK - 1) / PTS_BLK;   // 625 for P=40000
    PeriodicConvolutionPrep_fused<<<blocks, THREADS>>>(features, radii, W, bs, out, P);
}

// round 11
// speedup vs baseline: 1.2062x; 1.2062x over previous
#include <cuda_runtime.h>
#include <cuda_bf16.h>

#define CI 16
#define CO 16
#define DEG 16
#define BSROW (1 + DEG)            // 17 ints per bs_slice row

#define THREADS 128
#define NITER 8
#define PTS_BLK 64                 // 8 iters * 8 point-groups
#define GPAD 52                    // s_g row stride (floats): conflict-free

typedef unsigned long long u64;

__device__ __forceinline__ void fma2(u64 &d, u64 a, u64 b) {
    asm("fma.rn.f32x2 %0, %1, %2, %0;" : "+l"(d) : "l"(a), "l"(b));
}
__device__ __forceinline__ float2 upk2(u64 v) {
    float2 f; asm("mov.b64 {%0, %1}, %2;" : "=f"(f.x), "=f"(f.y) : "l"(v)); return f;
}

// out[p,o] = sum_j sum_d radii[p*DEG+j,d] * sum_i W[d,o,i] * features[nbr(p,j),i]
// Factored: g_d[i] = sum_j r_jd * f[nbr_j,i];  out[o] = sum_{d,i} W[d,o,i] * g_d[i]
//
// Phase 1 (R8-proven): 16 lanes/pt (q,c4), 4 independent LDG.128 gathers per
//   lane-iter, idx words preloaded, feature+radii prefetched 1 iter ahead,
//   shfl_xor(4)/(8) q-reduce, then ONE predicated STS.128 of g into s_g.
// Phase 2 (new): point-per-lane-pair. lane=(p16, oh): point p16, outputs
//   oh*8..+7. W read BROADCAST from smem (uniform per half-warp), g via
//   conflict-free private LDS.128, math in packed fp32x2 (fma.rn.f32x2),
//   fully coalesced output stores. No W-LDS per point-pair, no c4 shfl.
__global__ __launch_bounds__(THREADS)
void PeriodicConvolutionPrep_fused(
    const float* __restrict__ features,   // [P, CI]
    const float* __restrict__ radii,      // [P*DEG, 3]
    const float* __restrict__ W,          // [3, CO, CI]
    const int*   __restrict__ bs,         // [P, 1+DEG]
    float*       __restrict__ out,        // [P, CO]
    int P)
{
    __shared__ float  s_g[PTS_BLK][GPAD];     // 13.3 KB: g rows, stride 52
    __shared__ float4 s_w2[12][16];           // 3 KB: s_w2[d*4+cq][o] = W[d][o][4cq..+3]

    const int tid   = threadIdx.x;
    const int t16   = tid & 15;
    const int q     = t16 >> 2;          // neighbor quad / d-slice for STS
    const int c4    = t16 & 3;           // channel quad
    const int pt    = tid >> 4;          // point group within block (0..7)
    const int wrp   = tid >> 5;
    const int lane  = tid & 31;
    const int gbase = lane & ~15;

    const int base   = blockIdx.x * PTS_BLK;
    const int nvalid = min(PTS_BLK, P - base);

    // ---- stage W for phase 2: 192 float4, coalesced-ish, once per block ----
    {
        const float4* w4 = (const float4*)W;
        for (int t = tid; t < 192; t += THREADS) {
            const int kb = t >> 4, o = t & 15;
            const int d = kb >> 2, cq = kb & 3;
            s_w2[kb][o] = __ldg(w4 + (size_t)d * 64 + o * 4 + cq);
        }
    }

    // ---- point ids + preload ALL iterations' index words ----
    int  p[NITER];
    bool valid[NITER];
    int  myv[NITER];
#pragma unroll
    for (int it = 0; it < NITER; it++) {
        int pp = base + it * 8 + pt;
        valid[it] = (pp < P);
        p[it] = valid[it] ? pp : (P - 1);
        myv[it] = __ldg(bs + (size_t)p[it] * BSROW + 1 + t16);
    }

    // ---- double-buffered prefetch of features + radii (R8 structure) ----
    float4 fpre[2][4];
    float4 rpre[2][3];
    const float4* fb4 = (const float4*)features;

    auto issue_loads = [&](int it, int slot) {
        const int m  = myv[it];
        const int i0 = __shfl_sync(0xffffffffu, m, gbase + 4 * q + 0);
        const int i1 = __shfl_sync(0xffffffffu, m, gbase + 4 * q + 1);
        const int i2 = __shfl_sync(0xffffffffu, m, gbase + 4 * q + 2);
        const int i3 = __shfl_sync(0xffffffffu, m, gbase + 4 * q + 3);
        fpre[slot][0] = __ldg(fb4 + (size_t)i0 * (CI / 4) + c4);
        fpre[slot][1] = __ldg(fb4 + (size_t)i1 * (CI / 4) + c4);
        fpre[slot][2] = __ldg(fb4 + (size_t)i2 * (CI / 4) + c4);
        fpre[slot][3] = __ldg(fb4 + (size_t)i3 * (CI / 4) + c4);
        const float4* rp = (const float4*)(radii + ((size_t)p[it] * DEG + 4 * q) * 3);
        rpre[slot][0] = __ldg(rp + 0);
        rpre[slot][1] = __ldg(rp + 1);
        rpre[slot][2] = __ldg(rp + 2);
    };

    issue_loads(0, 0);

    // ================= Phase 1 =================
#pragma unroll
    for (int it = 0; it < NITER; it++) {
        const int slot = it & 1;
        if (it + 1 < NITER)
            issue_loads(it + 1, (it + 1) & 1);

        const float4 f0 = fpre[slot][0];
        const float4 f1 = fpre[slot][1];
        const float4 f2 = fpre[slot][2];
        const float4 f3 = fpre[slot][3];
        const float4 rv0 = rpre[slot][0];
        const float4 rv1 = rpre[slot][1];
        const float4 rv2 = rpre[slot][2];
        const float r[12] = { rv0.x, rv0.y, rv0.z, rv0.w, rv1.x, rv1.y,
                              rv1.z, rv1.w, rv2.x, rv2.y, rv2.z, rv2.w };

        float g[12];
#pragma unroll
        for (int d = 0; d < 3; d++) {
            g[d * 4 + 0] = r[0 * 3 + d] * f0.x;
            g[d * 4 + 1] = r[0 * 3 + d] * f0.y;
            g[d * 4 + 2] = r[0 * 3 + d] * f0.z;
            g[d * 4 + 3] = r[0 * 3 + d] * f0.w;
            g[d * 4 + 0] = fmaf(r[1 * 3 + d], f1.x, g[d * 4 + 0]);
            g[d * 4 + 1] = fmaf(r[1 * 3 + d], f1.y, g[d * 4 + 1]);
            g[d * 4 + 2] = fmaf(r[1 * 3 + d], f1.z, g[d * 4 + 2]);
            g[d * 4 + 3] = fmaf(r[1 * 3 + d], f1.w, g[d * 4 + 3]);
            g[d * 4 + 0] = fmaf(r[2 * 3 + d], f2.x, g[d * 4 + 0]);
            g[d * 4 + 1] = fmaf(r[2 * 3 + d], f2.y, g[d * 4 + 1]);
            g[d * 4 + 2] = fmaf(r[2 * 3 + d], f2.z, g[d * 4 + 2]);
            g[d * 4 + 3] = fmaf(r[2 * 3 + d], f2.w, g[d * 4 + 3]);
            g[d * 4 + 0] = fmaf(r[3 * 3 + d], f3.x, g[d * 4 + 0]);
            g[d * 4 + 1] = fmaf(r[3 * 3 + d], f3.y, g[d * 4 + 1]);
            g[d * 4 + 2] = fmaf(r[3 * 3 + d], f3.z, g[d * 4 + 2]);
            g[d * 4 + 3] = fmaf(r[3 * 3 + d], f3.w, g[d * 4 + 3]);
        }

        // reduce over q: every lane ends with full g_d for its c4 quad
#pragma unroll
        for (int v = 0; v < 12; v++) g[v] += __shfl_xor_sync(0xffffffffu, g[v], 4);
#pragma unroll
        for (int v = 0; v < 12; v++) g[v] += __shfl_xor_sync(0xffffffffu, g[v], 8);

        // lane (q<3, c4) stores d=q slice: ONE predicated STS.128
        if (q < 3 && valid[it])
            *(float4*)&s_g[it * 8 + pt][q * CI + 4 * c4] =
                make_float4(g[q * 4 + 0], g[q * 4 + 1], g[q * 4 + 2], g[q * 4 + 3]);
    }

    __syncthreads();

    // ================= Phase 2: packed f32x2, uniform W =================
    {
        const int p16 = lane & 15;           // point within warp's 16
        const int oh  = lane >> 4;           // output half (o = oh*8 .. +7)
        const int pL  = wrp * 16 + p16;      // local point 0..63

        if (pL < nvalid) {
            u64 acc[8];
#pragma unroll
            for (int oo = 0; oo < 8; oo++) acc[oo] = 0ull;   // (0.f, 0.f)

#pragma unroll
            for (int kb = 0; kb < 12; kb++) {                // (d, ch-quad)
                const ulonglong2 gv = *(const ulonglong2*)&s_g[pL][kb * 4];
#pragma unroll
                for (int oo = 0; oo < 8; oo++) {
                    const ulonglong2 wv = *(const ulonglong2*)&s_w2[kb][oh * 8 + oo];
                    fma2(acc[oo], wv.x, gv.x);               // even/odd-k partials
                    fma2(acc[oo], wv.y, gv.y);
                }
            }

            float res[8];
#pragma unroll
            for (int oo = 0; oo < 8; oo++) {
                const float2 f = upk2(acc[oo]);
                res[oo] = f.x + f.y;
            }
            // coalesced: 16 consecutive rows * 64B per warp
            float4* op = (float4*)(out + (size_t)(base + pL) * CO + oh * 8);
            op[0] = make_float4(res[0], res[1], res[2], res[3]);
            op[1] = make_float4(res[4], res[5], res[6], res[7]);
        }
    }
}

extern "C" void kernel_launch(void* const* d_in, const int* in_sizes, int n_in,
                              void* d_out, int out_size) {
    const float* features = (const float*)d_in[0];
    const float* radii    = (const float*)d_in[1];
    const float* W        = (const float*)d_in[2];
    const int*   bs       = (const int*)d_in[3];
    float*       out      = (float*)d_out;

    const int P = in_sizes[0] / CI;
    const int blocks = (P + PTS_BLK - 1) / PTS_BLK;   // 625 for P=40000
    PeriodicConvolutionPrep_fused<<<blocks, THREADS>>>(features, radii, W, bs, out, P);
}